// round 3
// baseline (speedup 1.0000x reference)
#include <cuda_runtime.h>
#include <math.h>

#define NB 64
#define CC 64
#define TT 256
#define VV 25
#define SS 3
#define II 16

// ---------------- device scratch ----------------
__device__ float g_A1 [NB*SS*VV*VV];   // raw inner products
__device__ float g_Ai [NB*SS*VV*VV];   // PA + alpha*tanh(A1/4096)
__device__ float g_y0 [NB*CC*TT*VV];   // post BN+relu tensor (~105MB)
__device__ float g_ST [NB*CC*VV];      // sum over T of y0
__device__ float g_SVw[NB*CC*TT];      // sum over V of y0*(1+gs[v])
__device__ float g_gs [NB*VV];         // 1+sigmoid spatial gate
__device__ float g_gt [NB*TT];         // 1+sigmoid temporal gate
__device__ float g_gc [NB*CC];         // 1+sigmoid channel gate

__device__ __forceinline__ float sigm(float x) { return 1.0f / (1.0f + expf(-x)); }

// ---------------- K0: zero atomic accumulators ----------------
__global__ void k0_zero() {
    const int tot = NB*SS*VV*VV + NB*CC*VV;
    for (int i = blockIdx.x*blockDim.x + threadIdx.x; i < tot; i += gridDim.x*blockDim.x) {
        if (i < NB*SS*VV*VV) g_A1[i] = 0.f;
        else                 g_ST[i - NB*SS*VV*VV] = 0.f;
    }
}

// ---------------- K1: embeddings + partial A1 ----------------
// grid (8 t-chunks, 64 n), 256 threads
__global__ __launch_bounds__(256) void k1_emb_adj(
    const float* __restrict__ x,  const float* __restrict__ Wa, const float* __restrict__ ba,
    const float* __restrict__ Wb, const float* __restrict__ bb)
{
    __shared__ __align__(16) float Xs[64*100];   // [c][t*25+v] flat, 4 t per sub-chunk
    __shared__ __align__(16) float Es[3204];     // rows 0..15 = a, 16..31 = b, stride 100
    __shared__ __align__(16) float Ws[32*65];    // padded
    __shared__ __align__(16) float bs[32];

    const int tid = threadIdx.x;
    const int n   = blockIdx.y;

    float accA0[SS], accA1[SS], accA2[SS], accA3[SS];
    #pragma unroll
    for (int s = 0; s < SS; ++s) { accA0[s]=0.f; accA1[s]=0.f; accA2[s]=0.f; accA3[s]=0.f; }
    const bool hasA = tid < 175;
    const int  vA = tid / 7, w4A = tid % 7;

    const bool hasE = tid < 200;
    const int  jg = tid / 25, q = tid % 25;   // jg: 4-j group (0..7), q: tv4 group

    for (int sub = 0; sub < 8; ++sub) {
        // float4 row-chunk index: each 4-t tile = 100 floats = 25 float4
        const int tile = blockIdx.x * 8 + sub;   // == t0/4
        __syncthreads();
        {   // load X tile as float4
            const float4* xg = (const float4*)x;
            float4* Xs4 = (float4*)Xs;
            for (int i = tid; i < 1600; i += 256) {
                int c = i / 25, qq = i - c*25;
                Xs4[c*25 + qq] = xg[(n*64 + c)*1600 + tile*25 + qq];
            }
        }
        __syncthreads();

        for (int s = 0; s < SS; ++s) {
            for (int i = tid; i < 2048; i += 256) {
                int j = i >> 6, c = i & 63;
                Ws[j*65 + c] = (j < 16) ? Wa[(s*16 + j)*64 + c]
                                        : Wb[(s*16 + (j-16))*64 + c];
            }
            if (tid < 32) bs[tid] = (tid < 16) ? ba[s*16 + tid] : bb[s*16 + (tid-16)];
            __syncthreads();

            // embeddings: 4-j register blocking
            if (hasE) {
                const float4* Xs4 = (const float4*)Xs;
                float4 a0, a1, a2, a3;
                float b0 = bs[jg*4+0], b1 = bs[jg*4+1], b2 = bs[jg*4+2], b3 = bs[jg*4+3];
                a0 = make_float4(b0,b0,b0,b0); a1 = make_float4(b1,b1,b1,b1);
                a2 = make_float4(b2,b2,b2,b2); a3 = make_float4(b3,b3,b3,b3);
                #pragma unroll 8
                for (int c = 0; c < 64; ++c) {
                    float4 xv = Xs4[c*25 + q];
                    float w0 = Ws[(jg*4+0)*65 + c], w1 = Ws[(jg*4+1)*65 + c];
                    float w2 = Ws[(jg*4+2)*65 + c], w3 = Ws[(jg*4+3)*65 + c];
                    a0.x += w0*xv.x; a0.y += w0*xv.y; a0.z += w0*xv.z; a0.w += w0*xv.w;
                    a1.x += w1*xv.x; a1.y += w1*xv.y; a1.z += w1*xv.z; a1.w += w1*xv.w;
                    a2.x += w2*xv.x; a2.y += w2*xv.y; a2.z += w2*xv.z; a2.w += w2*xv.w;
                    a3.x += w3*xv.x; a3.y += w3*xv.y; a3.z += w3*xv.z; a3.w += w3*xv.w;
                }
                float4* Es4 = (float4*)Es;
                Es4[(jg*4+0)*25 + q] = a0; Es4[(jg*4+1)*25 + q] = a1;
                Es4[(jg*4+2)*25 + q] = a2; Es4[(jg*4+3)*25 + q] = a3;
            }
            __syncthreads();

            // A1 partial: acc[v][w] += sum_{j<16,t<4} a[j,t,v]*b[j,t,w]
            if (hasA) {
                float c0 = accA0[s], c1 = accA1[s], c2 = accA2[s], c3 = accA3[s];
                #pragma unroll 4
                for (int j = 0; j < 16; ++j) {
                    #pragma unroll
                    for (int t = 0; t < 4; ++t) {
                        float  av = Es[j*100 + t*25 + vA];
                        const float* br = &Es[(16+j)*100 + t*25 + w4A*4];
                        c0 += av*br[0]; c1 += av*br[1]; c2 += av*br[2]; c3 += av*br[3];
                    }
                }
                accA0[s] = c0; accA1[s] = c1; accA2[s] = c2; accA3[s] = c3;
            }
            __syncthreads();
        }
    }

    if (hasA) {
        #pragma unroll
        for (int s = 0; s < SS; ++s) {
            float* dst = &g_A1[((n*SS + s)*VV + vA)*VV];
            float vals[4] = {accA0[s], accA1[s], accA2[s], accA3[s]};
            #pragma unroll
            for (int k = 0; k < 4; ++k) {
                int w = w4A*4 + k;
                if (w < VV) atomicAdd(&dst[w], vals[k]);
            }
        }
    }
}

// ---------------- K2: Ai = PA + alpha * tanh(A1/4096) ----------------
__global__ void k2_adj(const float* __restrict__ PA, const float* __restrict__ alpha) {
    const float al = alpha[0];
    const int tot = NB*SS*VV*VV;
    for (int i = blockIdx.x*blockDim.x + threadIdx.x; i < tot; i += gridDim.x*blockDim.x)
        g_Ai[i] = PA[i % (SS*VV*VV)] + al * tanhf(g_A1[i] * (1.0f/4096.0f));
}

// ---------------- K3: main fused compute ----------------
// grid (64 t-tiles of 4, 64 n), 128 threads, dyn smem 73712 B
__global__ __launch_bounds__(128, 3) void k3_main(
    const float* __restrict__ x,  const float* __restrict__ Wd, const float* __restrict__ bd,
    const float* __restrict__ gamma, const float* __restrict__ beta)
{
    extern __shared__ float sm[];
    float* Xs  = sm;            // [64][100] flat   (6400)
    float* Zs  = sm + 6400;     // [64][112] padded (7168)
    float* Ais = sm + 13568;    // [25][28] padded  (700)
    float* Wds = sm + 14268;    // [64][65] padded  (4160)

    const int tid = threadIdx.x;
    const int n   = blockIdx.y;
    const int tile = blockIdx.x;          // 4-t tile; float4 row offset = tile*25
    const int o2  = tid >> 2, tq = tid & 3;
    const int o0  = o2*2, o1 = o0 + 1;

    // zero Ai padding columns (cols 25..27)
    if (tid < 75) Ais[(tid/3)*28 + 25 + (tid%3)] = 0.f;
    {   // load X tile (float4)
        const float4* xg = (const float4*)x;
        float4* Xs4 = (float4*)Xs;
        for (int i = tid; i < 1600; i += 128) {
            int c = i / 25, qq = i - c*25;
            Xs4[c*25 + qq] = xg[(n*64 + c)*1600 + tile*25 + qq];
        }
    }

    float accA[28], accB[28];
    #pragma unroll
    for (int k = 0; k < 28; ++k) { accA[k] = 0.f; accB[k] = 0.f; }

    for (int s = 0; s < SS; ++s) {
        __syncthreads();   // protect Ais/Wds/Zs from previous iteration readers
        for (int i = tid; i < 625;  i += 128) Ais[(i/25)*28 + (i%25)] = g_Ai[(n*SS + s)*625 + i];
        for (int i = tid; i < 4096; i += 128) Wds[(i>>6)*65 + (i&63)] = Wd[s*4096 + i];
        __syncthreads();

        // Z[c][t][w] = sum_v X[c][t][v] * Ai[v][w]  (each thread: 2 rows)
        {
            const float4* Ai4 = (const float4*)Ais;
            float4* Zs4 = (float4*)Zs;
            for (int idx = tid; idx < 256; idx += 128) {
                int c = idx >> 2, tz = idx & 3;
                float xr[25];
                #pragma unroll
                for (int v = 0; v < 25; ++v) xr[v] = Xs[c*100 + tz*25 + v];
                #pragma unroll
                for (int w4 = 0; w4 < 7; ++w4) {
                    float4 a = make_float4(0.f,0.f,0.f,0.f);
                    #pragma unroll
                    for (int v = 0; v < 25; ++v) {
                        float4 av = Ai4[v*7 + w4];
                        float xv = xr[v];
                        a.x += xv*av.x; a.y += xv*av.y; a.z += xv*av.z; a.w += xv*av.w;
                    }
                    Zs4[c*28 + tz*7 + w4] = a;
                }
            }
        }
        __syncthreads();

        // Y[o][t][w] += sum_c Wd[o][c] * Z[c][t][w]  (2-o register blocking)
        {
            const float4* Zs4 = (const float4*)Zs;
            #pragma unroll 4
            for (int c = 0; c < 64; ++c) {
                float wa = Wds[o0*65 + c];
                float wb = Wds[o1*65 + c];
                #pragma unroll
                for (int w4 = 0; w4 < 7; ++w4) {
                    float4 z = Zs4[c*28 + tq*7 + w4];
                    accA[4*w4+0] += wa*z.x; accA[4*w4+1] += wa*z.y;
                    accA[4*w4+2] += wa*z.z; accA[4*w4+3] += wa*z.w;
                    accB[4*w4+0] += wb*z.x; accB[4*w4+1] += wb*z.y;
                    accB[4*w4+2] += wb*z.z; accB[4*w4+3] += wb*z.w;
                }
            }
        }
    }
    __syncthreads();   // all Zs reads done

    // epilogue: bias + BN + residual + relu
    const float bsA = bd[o0] + bd[64+o0] + bd[128+o0];
    const float bsB = bd[o1] + bd[64+o1] + bd[128+o1];
    const float scl = rsqrtf(1.0f + 1e-5f);
    const float scA = gamma[o0]*scl, scB = gamma[o1]*scl;
    const float btA = beta[o0],      btB = beta[o1];
    #pragma unroll
    for (int w = 0; w < 25; ++w) {
        float ya = (accA[w] + bsA)*scA + btA + Xs[o0*100 + tq*25 + w];
        float yb = (accB[w] + bsB)*scB + btB + Xs[o1*100 + tq*25 + w];
        accA[w] = fmaxf(ya, 0.f);
        accB[w] = fmaxf(yb, 0.f);
    }

    // reduce over t (groups of 4 lanes) for the T-sum
    float sA[25], sB[25];
    #pragma unroll
    for (int w = 0; w < 25; ++w) {
        float a = accA[w], b = accB[w];
        a += __shfl_down_sync(0xffffffffu, a, 2, 4);
        a += __shfl_down_sync(0xffffffffu, a, 1, 4);
        b += __shfl_down_sync(0xffffffffu, b, 2, 4);
        b += __shfl_down_sync(0xffffffffu, b, 1, 4);
        sA[w] = a; sB[w] = b;
    }
    __syncthreads();   // everyone done reading Xs (residual) & Zs
    // stage y0 in Zs (flat stride 100), T-sums in Xs (flat stride 25)
    #pragma unroll
    for (int w = 0; w < 25; ++w) {
        Zs[o0*100 + tq*25 + w] = accA[w];
        Zs[o1*100 + tq*25 + w] = accB[w];
    }
    if (tq == 0) {
        #pragma unroll
        for (int w = 0; w < 25; ++w) { Xs[o0*25 + w] = sA[w]; Xs[o1*25 + w] = sB[w]; }
    }
    __syncthreads();

    {   // coalesced y0 store + global ST accumulate
        float4* yg = (float4*)g_y0;
        const float4* Zs4 = (const float4*)Zs;
        for (int i = tid; i < 1600; i += 128) {
            int c = i / 25, qq = i - c*25;
            yg[(n*64 + c)*1600 + tile*25 + qq] = Zs4[c*25 + qq];
        }
        for (int i = tid; i < 1600; i += 128)
            atomicAdd(&g_ST[n*1600 + i], Xs[i]);
    }
}

// ---------------- K4: spatial gate ----------------
__global__ __launch_bounds__(128) void k4_sgate(const float* __restrict__ Wsa,
                                                const float* __restrict__ bsa)
{
    __shared__ float se[1600];
    __shared__ float wk[1600];
    const int tid = threadIdx.x, n = blockIdx.x;
    for (int i = tid; i < 1600; i += 128) {
        se[i] = g_ST[n*1600 + i] * (1.0f/256.0f);
        wk[i] = Wsa[i];
    }
    __syncthreads();
    if (tid < VV) {
        int v = tid;
        float acc = bsa[0];
        for (int c = 0; c < 64; ++c)
            #pragma unroll
            for (int k = 0; k < 25; ++k) {
                int u = v + k - 12;
                if (u >= 0 && u < 25) acc += wk[c*25 + k] * se[c*25 + u];
            }
        g_gs[n*25 + v] = 1.0f + sigm(acc);
    }
}

// ---------------- K5: SVw = sum_v y0*(1+gs) ----------------
__global__ __launch_bounds__(256) void k5_svw() {
    __shared__ float gs[25];
    const int c = blockIdx.x, n = blockIdx.y, t = threadIdx.x;
    if (t < 25) gs[t] = g_gs[n*25 + t];
    __syncthreads();
    const float* row = &g_y0[((n*64 + c)*256 + t)*25];
    float s = 0.f;
    #pragma unroll
    for (int v = 0; v < 25; ++v) s += row[v] * gs[v];
    g_SVw[(n*64 + c)*256 + t] = s;
}

// ---------------- K6: temporal gate ----------------
__global__ __launch_bounds__(256) void k6_tgate(const float* __restrict__ Wta,
                                                const float* __restrict__ bta)
{
    __shared__ float wk[576];
    const int tid = threadIdx.x, n = blockIdx.x;
    for (int i = tid; i < 576; i += 256) wk[i] = Wta[i];
    __syncthreads();
    const int t = tid;
    float s = 0.f;
    for (int c = 0; c < 64; ++c) {
        const float* sv = &g_SVw[(n*64 + c)*256];
        #pragma unroll
        for (int k = 0; k < 9; ++k) {
            int u = t + k - 4;
            if (u >= 0 && u < 256) s += wk[c*9 + k] * sv[u];
        }
    }
    float acc = bta[0] + s * (1.0f/25.0f);
    g_gt[n*256 + t] = 1.0f + sigm(acc);
}

// ---------------- K7: channel gate ----------------
__global__ __launch_bounds__(64) void k7_cgate(
    const float* __restrict__ W1, const float* __restrict__ b1,
    const float* __restrict__ W2, const float* __restrict__ b2)
{
    __shared__ float gt[256];
    __shared__ float se[64];
    __shared__ float h[32];
    const int tid = threadIdx.x, n = blockIdx.x;
    for (int i = tid; i < 256; i += 64) gt[i] = g_gt[n*256 + i];
    __syncthreads();
    {
        const float* sv = &g_SVw[(n*64 + tid)*256];
        float s = 0.f;
        for (int t = 0; t < 256; ++t) s += sv[t] * gt[t];
        se[tid] = s * (1.0f/6400.0f);
    }
    __syncthreads();
    if (tid < 32) {
        float a = b1[tid];
        for (int c = 0; c < 64; ++c) a += W1[tid*64 + c] * se[c];
        h[tid] = fmaxf(a, 0.f);
    }
    __syncthreads();
    {
        float a = b2[tid];
        #pragma unroll
        for (int j = 0; j < 32; ++j) a += W2[tid*32 + j] * h[j];
        g_gc[n*64 + tid] = 1.0f + sigm(a);
    }
}

// ---------------- K8: finalize out = y0*(1+gs)(1+gt)(1+gc) ----------------
__global__ __launch_bounds__(1024) void k8_final(float* __restrict__ out) {
    unsigned idx = blockIdx.x*1024u + threadIdx.x;
    if (idx >= (unsigned)(NB*CC*TT*VV)) return;
    unsigned r  = idx / 25u;
    unsigned v  = idx - r*25u;
    unsigned t  = r & 255u;
    unsigned nc = r >> 8;
    unsigned n  = nc >> 6;
    out[idx] = g_y0[idx] * g_gs[n*25 + v] * g_gt[n*256 + t] * g_gc[nc];
}

// ---------------- launch ----------------
extern "C" void kernel_launch(void* const* d_in, const int* in_sizes, int n_in,
                              void* d_out, int out_size) {
    const float* x     = (const float*)d_in[0];
    const float* PA    = (const float*)d_in[1];
    const float* alpha = (const float*)d_in[2];
    const float* Wa    = (const float*)d_in[3];
    const float* ba    = (const float*)d_in[4];
    const float* Wb    = (const float*)d_in[5];
    const float* bb    = (const float*)d_in[6];
    const float* Wd    = (const float*)d_in[7];
    const float* bd    = (const float*)d_in[8];
    const float* gam   = (const float*)d_in[9];
    const float* bet   = (const float*)d_in[10];
    const float* Wsa   = (const float*)d_in[11];
    const float* bsa   = (const float*)d_in[12];
    const float* Wta   = (const float*)d_in[13];
    const float* bta   = (const float*)d_in[14];
    const float* W1    = (const float*)d_in[15];
    const float* b1    = (const float*)d_in[16];
    const float* W2    = (const float*)d_in[17];
    const float* b2    = (const float*)d_in[18];
    float* out = (float*)d_out;

    cudaFuncSetAttribute(k3_main, cudaFuncAttributeMaxDynamicSharedMemorySize, 75000);

    k0_zero<<<224, 1024>>>();
    k1_emb_adj<<<dim3(8, 64), 256>>>(x, Wa, ba, Wb, bb);
    k2_adj<<<120, 1024>>>(PA, alpha);
    k3_main<<<dim3(64, 64), 128, 73712>>>(x, Wd, bd, gam, bet);
    k4_sgate<<<64, 128>>>(Wsa, bsa);
    k5_svw<<<dim3(64, 64), 256>>>();
    k6_tgate<<<64, 256>>>(Wta, bta);
    k7_cgate<<<64, 64>>>(W1, b1, W2, b2);
    k8_final<<<25600, 1024>>>(out);
}

// round 7
// speedup vs baseline: 1.0275x; 1.0275x over previous
#include <cuda_runtime.h>
#include <math.h>

#define NB 64
#define CC 64
#define TT 256
#define VV 25
#define SS 3
#define II 16

typedef unsigned long long ull;

// ---------------- device scratch ----------------
__device__ float g_A1 [NB*SS*VV*VV];
__device__ float g_Ai [NB*SS*VV*VV];
__device__ float g_y0 [NB*CC*TT*VV];   // ~105MB
__device__ float g_ST [NB*CC*VV];
__device__ float g_SVw[NB*CC*TT];
__device__ float g_gs [NB*VV];
__device__ float g_gt [NB*TT];
__device__ float g_gc [NB*CC];

__device__ __forceinline__ float sigm(float x) { return 1.0f / (1.0f + expf(-x)); }

// packed fp32x2 helpers (FFMA2 path — 2x fp32 throughput, PTX-only)
__device__ __forceinline__ ull pack2(float f) {
    ull r;
    asm("mov.b64 %0, {%1, %1};" : "=l"(r) : "r"(__float_as_uint(f)));
    return r;
}
__device__ __forceinline__ void fma2(ull& d, ull a, ull b) {
    asm("fma.rn.f32x2 %0, %1, %2, %0;" : "+l"(d) : "l"(a), "l"(b));
}
__device__ __forceinline__ float2 unpack2(ull p) {
    unsigned lo, hi;
    asm("mov.b64 {%0, %1}, %2;" : "=r"(lo), "=r"(hi) : "l"(p));
    return make_float2(__uint_as_float(lo), __uint_as_float(hi));
}

// ---------------- K0: zero atomic accumulators ----------------
__global__ void k0_zero() {
    const int tot = NB*SS*VV*VV + NB*CC*VV;
    for (int i = blockIdx.x*blockDim.x + threadIdx.x; i < tot; i += gridDim.x*blockDim.x) {
        if (i < NB*SS*VV*VV) g_A1[i] = 0.f;
        else                 g_ST[i - NB*SS*VV*VV] = 0.f;
    }
}

// ---------------- K1: embeddings + partial A1 ----------------
// grid (8 t-chunks, 64 n), 256 threads
__global__ __launch_bounds__(256) void k1_emb_adj(
    const float* __restrict__ x,  const float* __restrict__ Wa, const float* __restrict__ ba,
    const float* __restrict__ Wb, const float* __restrict__ bb)
{
    __shared__ __align__(16) float Xs[64*100];   // [c][t*25+v] flat (4 t per sub-chunk)
    __shared__ __align__(16) float Es[32*112];   // rows 0..15 = a, 16..31 = b; stride 112,
                                                 // within-row layout FLAT: t*25+v in [0,100)
    __shared__ __align__(16) float Ws[32*65];
    __shared__ __align__(16) float bs[32];

    const int tid = threadIdx.x;
    const int n   = blockIdx.y;

    float accA0[SS], accA1[SS], accA2[SS], accA3[SS];
    #pragma unroll
    for (int s = 0; s < SS; ++s) { accA0[s]=0.f; accA1[s]=0.f; accA2[s]=0.f; accA3[s]=0.f; }
    const bool hasA = tid < 175;
    const int  vA = tid / 7, w4A = tid % 7;

    const bool hasE = tid < 200;
    const int  jg = tid / 25, q = tid % 25;

    for (int sub = 0; sub < 8; ++sub) {
        const int tile = blockIdx.x * 8 + sub;      // 4-t tile index (float4 row = 25)
        __syncthreads();
        {
            const float4* xg = (const float4*)x;
            float4* Xs4 = (float4*)Xs;
            for (int i = tid; i < 1600; i += 256) {
                int c = i / 25, qq = i - c*25;
                Xs4[c*25 + qq] = xg[(n*64 + c)*1600 + tile*25 + qq];
            }
        }
        __syncthreads();

        for (int s = 0; s < SS; ++s) {
            for (int i = tid; i < 2048; i += 256) {
                int j = i >> 6, c = i & 63;
                Ws[j*65 + c] = (j < 16) ? Wa[(s*16 + j)*64 + c]
                                        : Wb[(s*16 + (j-16))*64 + c];
            }
            if (tid < 32) bs[tid] = (tid < 16) ? ba[s*16 + tid] : bb[s*16 + (tid-16)];
            __syncthreads();

            // embeddings: 4-j blocking, FFMA2 (writes flat [0,100) region of each row)
            if (hasE) {
                const ulonglong2* Xs2 = (const ulonglong2*)Xs;
                ull a0x = pack2(bs[jg*4+0]), a0y = a0x;
                ull a1x = pack2(bs[jg*4+1]), a1y = a1x;
                ull a2x = pack2(bs[jg*4+2]), a2y = a2x;
                ull a3x = pack2(bs[jg*4+3]), a3y = a3x;
                #pragma unroll 8
                for (int c = 0; c < 64; ++c) {
                    ulonglong2 xv = Xs2[c*25 + q];
                    ull w0 = pack2(Ws[(jg*4+0)*65 + c]);
                    ull w1 = pack2(Ws[(jg*4+1)*65 + c]);
                    ull w2 = pack2(Ws[(jg*4+2)*65 + c]);
                    ull w3 = pack2(Ws[(jg*4+3)*65 + c]);
                    fma2(a0x, w0, xv.x); fma2(a0y, w0, xv.y);
                    fma2(a1x, w1, xv.x); fma2(a1y, w1, xv.y);
                    fma2(a2x, w2, xv.x); fma2(a2y, w2, xv.y);
                    fma2(a3x, w3, xv.x); fma2(a3y, w3, xv.y);
                }
                ulonglong2* Es2 = (ulonglong2*)Es;
                Es2[(jg*4+0)*28 + q] = make_ulonglong2(a0x, a0y);
                Es2[(jg*4+1)*28 + q] = make_ulonglong2(a1x, a1y);
                Es2[(jg*4+2)*28 + q] = make_ulonglong2(a2x, a2y);
                Es2[(jg*4+3)*28 + q] = make_ulonglong2(a3x, a3y);
            }
            __syncthreads();

            // A1 partial: acc[v][w] += sum_{j,t} a[j,t,v]*b[j,t,w]
            // FLAT within-row addressing (t*25+v); scalar loads
            if (hasA) {
                float c0 = accA0[s], c1 = accA1[s], c2 = accA2[s], c3 = accA3[s];
                #pragma unroll 4
                for (int j = 0; j < 16; ++j) {
                    #pragma unroll
                    for (int t = 0; t < 4; ++t) {
                        float av = Es[j*112 + t*25 + vA];
                        const float* br = &Es[(16+j)*112 + t*25 + w4A*4];
                        c0 += av*br[0]; c1 += av*br[1]; c2 += av*br[2]; c3 += av*br[3];
                    }
                }
                accA0[s] = c0; accA1[s] = c1; accA2[s] = c2; accA3[s] = c3;
            }
            __syncthreads();
        }
    }

    if (hasA) {
        #pragma unroll
        for (int s = 0; s < SS; ++s) {
            float* dst = &g_A1[((n*SS + s)*VV + vA)*VV];
            float vals[4] = {accA0[s], accA1[s], accA2[s], accA3[s]};
            #pragma unroll
            for (int k = 0; k < 4; ++k) {
                int w = w4A*4 + k;
                if (w < VV) atomicAdd(&dst[w], vals[k]);
            }
        }
    }
}

// ---------------- K2: Ai = PA + alpha * tanh(A1/4096) ----------------
__global__ void k2_adj(const float* __restrict__ PA, const float* __restrict__ alpha) {
    const float al = alpha[0];
    const int tot = NB*SS*VV*VV;
    for (int i = blockIdx.x*blockDim.x + threadIdx.x; i < tot; i += gridDim.x*blockDim.x)
        g_Ai[i] = PA[i % (SS*VV*VV)] + al * tanhf(g_A1[i] * (1.0f/4096.0f));
}

// ---------------- K3: main fused compute (FFMA2) ----------------
// grid (64 t-tiles of 4, 64 n), 128 threads, dyn smem 48128 B
__global__ __launch_bounds__(128, 3) void k3_main(
    const float* __restrict__ x,  const float* __restrict__ Wd, const float* __restrict__ bd,
    const float* __restrict__ gamma, const float* __restrict__ beta)
{
    extern __shared__ float sm[];
    float* Zs  = sm;            // [64][112] padded (7168)
    float* Ais = sm + 7168;     // [25][28] padded  (704 incl align pad)
    float* Wds = sm + 7872;     // [64][65] padded  (4160)   total 12032 floats

    const int tid  = threadIdx.x;
    const int n    = blockIdx.y;
    const int tile = blockIdx.x;          // t0 = tile*4
    const int cz   = tid >> 2, tz = tid & 3;       // Z-stage rows (cz, tz), (cz+32, tz)
    const int o2   = tid >> 2, tq = tid & 3;       // GEMM mapping
    const int o0   = o2*2, o1 = o0 + 1;

    // hold both X rows in registers for the whole kernel
    float xr0[25], xr1[25];
    {
        const float* xp0 = x + (n*64 + cz)*6400 + (tile*4 + tz)*25;
        const float* xp1 = xp0 + 32*6400;
        #pragma unroll
        for (int v = 0; v < 25; ++v) { xr0[v] = xp0[v]; xr1[v] = xp1[v]; }
    }

    if (tid < 25) { Ais[tid*28+25] = 0.f; Ais[tid*28+26] = 0.f; Ais[tid*28+27] = 0.f; }

    ull accA[14], accB[14];
    #pragma unroll
    for (int k = 0; k < 14; ++k) { accA[k] = 0ULL; accB[k] = 0ULL; }

    for (int s = 0; s < SS; ++s) {
        __syncthreads();
        for (int i = tid; i < 625;  i += 128) Ais[(i/25)*28 + (i%25)] = g_Ai[(n*SS + s)*625 + i];
        for (int i = tid; i < 4096; i += 128) Wds[(i>>6)*65 + (i&63)] = Wd[s*4096 + i];
        __syncthreads();

        // Z[c][t][w] = sum_v X[c][t][v] * Ai[v][w]  — two rows per thread, FFMA2
        {
            const ulonglong2* Ai2 = (const ulonglong2*)Ais;
            #pragma unroll
            for (int r = 0; r < 2; ++r) {
                const float* xr = r ? xr1 : xr0;
                const int c = cz + r*32;
                ull z[14];
                #pragma unroll
                for (int k = 0; k < 14; ++k) z[k] = 0ULL;
                #pragma unroll
                for (int v = 0; v < 25; ++v) {
                    ull xv = pack2(xr[v]);
                    #pragma unroll
                    for (int w4 = 0; w4 < 7; ++w4) {
                        ulonglong2 a = Ai2[v*7 + w4];
                        fma2(z[2*w4], xv, a.x); fma2(z[2*w4+1], xv, a.y);
                    }
                }
                ulonglong2* zd = (ulonglong2*)(Zs + c*112 + tz*28);
                #pragma unroll
                for (int w4 = 0; w4 < 7; ++w4) zd[w4] = make_ulonglong2(z[2*w4], z[2*w4+1]);
            }
        }
        __syncthreads();

        // Y[o][t][w] += sum_c Wd[o][c] * Z[c][t][w]  — 2-o blocking, FFMA2
        #pragma unroll 4
        for (int c = 0; c < 64; ++c) {
            ull wa = pack2(Wds[o0*65 + c]);
            ull wb = pack2(Wds[o1*65 + c]);
            const ulonglong2* z2 = (const ulonglong2*)(Zs + c*112 + tq*28);
            #pragma unroll
            for (int w4 = 0; w4 < 7; ++w4) {
                ulonglong2 z = z2[w4];
                fma2(accA[2*w4], wa, z.x); fma2(accA[2*w4+1], wa, z.y);
                fma2(accB[2*w4], wb, z.x); fma2(accB[2*w4+1], wb, z.y);
            }
        }
    }
    __syncthreads();   // all Zs reads done

    // epilogue: unpack + bias + BN + residual + relu
    float ya[28], yb[28];
    #pragma unroll
    for (int k = 0; k < 14; ++k) {
        float2 fa = unpack2(accA[k]); ya[2*k] = fa.x; ya[2*k+1] = fa.y;
        float2 fb = unpack2(accB[k]); yb[2*k] = fb.x; yb[2*k+1] = fb.y;
    }
    {
        const float bsA = bd[o0] + bd[64+o0] + bd[128+o0];
        const float bsB = bd[o1] + bd[64+o1] + bd[128+o1];
        const float scl = rsqrtf(1.0f + 1e-5f);
        const float scA = gamma[o0]*scl, scB = gamma[o1]*scl;
        const float btA = beta[o0],      btB = beta[o1];
        const float* xA = x + (n*64 + o0)*6400 + (tile*4 + tq)*25;
        const float* xB = xA + 6400;
        #pragma unroll
        for (int w = 0; w < 25; ++w) {
            ya[w] = fmaxf((ya[w] + bsA)*scA + btA + xA[w], 0.f);
            yb[w] = fmaxf((yb[w] + bsB)*scB + btB + xB[w], 0.f);
        }
    }
    // stage y0 in Zs flat (c, t, v) stride 100
    #pragma unroll
    for (int w = 0; w < 25; ++w) {
        Zs[o0*100 + tq*25 + w] = ya[w];
        Zs[o1*100 + tq*25 + w] = yb[w];
    }
    __syncthreads();

    {   // coalesced y0 store + ST atomic accumulate (sum the 4 t's from Zs)
        float4* yg = (float4*)g_y0;
        const float4* Zs4 = (const float4*)Zs;
        for (int i = tid; i < 1600; i += 128) {
            int c = i / 25, qq = i - c*25;
            yg[(n*64 + c)*1600 + tile*25 + qq] = Zs4[c*25 + qq];
        }
        for (int i = tid; i < 1600; i += 128) {
            int c = i / 25, v = i - c*25;
            float ssum = Zs[c*100 + v] + Zs[c*100 + 25 + v]
                       + Zs[c*100 + 50 + v] + Zs[c*100 + 75 + v];
            atomicAdd(&g_ST[n*1600 + i], ssum);
        }
    }
}

// ---------------- K4: spatial gate ----------------
__global__ __launch_bounds__(128) void k4_sgate(const float* __restrict__ Wsa,
                                                const float* __restrict__ bsa)
{
    __shared__ float se[1600];
    __shared__ float wk[1600];
    const int tid = threadIdx.x, n = blockIdx.x;
    for (int i = tid; i < 1600; i += 128) {
        se[i] = g_ST[n*1600 + i] * (1.0f/256.0f);
        wk[i] = Wsa[i];
    }
    __syncthreads();
    if (tid < VV) {
        int v = tid;
        float acc = bsa[0];
        for (int c = 0; c < 64; ++c)
            #pragma unroll
            for (int k = 0; k < 25; ++k) {
                int u = v + k - 12;
                if (u >= 0 && u < 25) acc += wk[c*25 + k] * se[c*25 + u];
            }
        g_gs[n*25 + v] = 1.0f + sigm(acc);
    }
}

// ---------------- K5: SVw = sum_v y0*(1+gs) ----------------
__global__ __launch_bounds__(256) void k5_svw() {
    __shared__ float gs[25];
    const int c = blockIdx.x, n = blockIdx.y, t = threadIdx.x;
    if (t < 25) gs[t] = g_gs[n*25 + t];
    __syncthreads();
    const float* row = &g_y0[((n*64 + c)*256 + t)*25];
    float s = 0.f;
    #pragma unroll
    for (int v = 0; v < 25; ++v) s += row[v] * gs[v];
    g_SVw[(n*64 + c)*256 + t] = s;
}

// ---------------- K6: temporal gate ----------------
__global__ __launch_bounds__(256) void k6_tgate(const float* __restrict__ Wta,
                                                const float* __restrict__ bta)
{
    __shared__ float wk[576];
    const int tid = threadIdx.x, n = blockIdx.x;
    for (int i = tid; i < 576; i += 256) wk[i] = Wta[i];
    __syncthreads();
    const int t = tid;
    float s = 0.f;
    for (int c = 0; c < 64; ++c) {
        const float* sv = &g_SVw[(n*64 + c)*256];
        #pragma unroll
        for (int k = 0; k < 9; ++k) {
            int u = t + k - 4;
            if (u >= 0 && u < 256) s += wk[c*9 + k] * sv[u];
        }
    }
    float acc = bta[0] + s * (1.0f/25.0f);
    g_gt[n*256 + t] = 1.0f + sigm(acc);
}

// ---------------- K7: channel gate ----------------
__global__ __launch_bounds__(64) void k7_cgate(
    const float* __restrict__ W1, const float* __restrict__ b1,
    const float* __restrict__ W2, const float* __restrict__ b2)
{
    __shared__ float gt[256];
    __shared__ float se[64];
    __shared__ float h[32];
    const int tid = threadIdx.x, n = blockIdx.x;
    for (int i = tid; i < 256; i += 64) gt[i] = g_gt[n*256 + i];
    __syncthreads();
    {
        const float* sv = &g_SVw[(n*64 + tid)*256];
        float s = 0.f;
        for (int t = 0; t < 256; ++t) s += sv[t] * gt[t];
        se[tid] = s * (1.0f/6400.0f);
    }
    __syncthreads();
    if (tid < 32) {
        float a = b1[tid];
        for (int c = 0; c < 64; ++c) a += W1[tid*64 + c] * se[c];
        h[tid] = fmaxf(a, 0.f);
    }
    __syncthreads();
    {
        float a = b2[tid];
        #pragma unroll
        for (int j = 0; j < 32; ++j) a += W2[tid*32 + j] * h[j];
        g_gc[n*64 + tid] = 1.0f + sigm(a);
    }
}

// ---------------- K8: finalize out = y0*(1+gs)(1+gt)(1+gc) (float4) ----------------
__global__ __launch_bounds__(256) void k8_final(float* __restrict__ out) {
    const int i4 = blockIdx.x*256 + threadIdx.x;
    if (i4 >= NB*CC*TT*VV/4) return;
    float4 y = ((const float4*)g_y0)[i4];
    float r[4] = {y.x, y.y, y.z, y.w};
    #pragma unroll
    for (int k = 0; k < 4; ++k) {
        unsigned idx = (unsigned)i4*4u + k;
        unsigned row = idx / 25u;
        unsigned v   = idx - row*25u;
        unsigned t   = row & 255u;
        unsigned nc  = row >> 8;
        unsigned n   = nc >> 6;
        r[k] *= g_gs[n*25 + v] * g_gt[n*256 + t] * g_gc[nc];
    }
    ((float4*)out)[i4] = make_float4(r[0], r[1], r[2], r[3]);
}

// ---------------- launch ----------------
extern "C" void kernel_launch(void* const* d_in, const int* in_sizes, int n_in,
                              void* d_out, int out_size) {
    const float* x     = (const float*)d_in[0];
    const float* PA    = (const float*)d_in[1];
    const float* alpha = (const float*)d_in[2];
    const float* Wa    = (const float*)d_in[3];
    const float* ba    = (const float*)d_in[4];
    const float* Wb    = (const float*)d_in[5];
    const float* bb    = (const float*)d_in[6];
    const float* Wd    = (const float*)d_in[7];
    const float* bd    = (const float*)d_in[8];
    const float* gam   = (const float*)d_in[9];
    const float* bet   = (const float*)d_in[10];
    const float* Wsa   = (const float*)d_in[11];
    const float* bsa   = (const float*)d_in[12];
    const float* Wta   = (const float*)d_in[13];
    const float* bta   = (const float*)d_in[14];
    const float* W1    = (const float*)d_in[15];
    const float* b1    = (const float*)d_in[16];
    const float* W2    = (const float*)d_in[17];
    const float* b2    = (const float*)d_in[18];
    float* out = (float*)d_out;

    cudaFuncSetAttribute(k3_main, cudaFuncAttributeMaxDynamicSharedMemorySize, 50000);

    k0_zero<<<224, 1024>>>();
    k1_emb_adj<<<dim3(8, 64), 256>>>(x, Wa, ba, Wb, bb);
    k2_adj<<<120, 1024>>>(PA, alpha);
    k3_main<<<dim3(64, 64), 128, 48128>>>(x, Wd, bd, gam, bet);
    k4_sgate<<<64, 128>>>(Wsa, bsa);
    k5_svw<<<dim3(64, 64), 256>>>();
    k6_tgate<<<64, 256>>>(Wta, bta);
    k7_cgate<<<64, 64>>>(W1, b1, W2, b2);
    k8_final<<<25600, 256>>>(out);   // 26,214,400 floats / 4 / 256 = 25,600 blocks
}